// round 15
// baseline (speedup 1.0000x reference)
#include <cuda_runtime.h>
#include <cuda_bf16.h>
#include <stdint.h>
#include <math.h>

#define B_    256
#define D_    2048
#define NCAMS 6
#define P_    8192
#define A_    6
#define M_    49152
#define BG_KNN 50
#define POS_K  3
#define TOP_EXTRA 30
#define INV_BETA 20.0f

// ---------------- scratch -----------------------------------------------------
__device__ float g_sims[(size_t)B_ * M_];   // 50.3 MB
__device__ float g_ce[B_];
__device__ float g_as[B_];
__device__ float g_on[B_];

// ---------------- bf16 MMA helper ---------------------------------------------
__device__ __forceinline__ void mma16(float d[4], const uint32_t a[4], const uint32_t b[2]){
    asm volatile(
        "mma.sync.aligned.m16n8k16.row.col.f32.bf16.bf16.f32 "
        "{%0,%1,%2,%3}, {%4,%5,%6,%7}, {%8,%9}, {%0,%1,%2,%3};"
        : "+f"(d[0]), "+f"(d[1]), "+f"(d[2]), "+f"(d[3])
        : "r"(a[0]), "r"(a[1]), "r"(a[2]), "r"(a[3]), "r"(b[0]), "r"(b[1]));
}

// pack 4 consecutive fp32 -> 2 bf16x2 regs, store 8B to smem
__device__ __forceinline__ void sts_bf16x4(uint32_t addr, float4 v){
    uint32_t u0, u1;
    asm("cvt.rn.bf16x2.f32 %0, %1, %2;" : "=r"(u0) : "f"(v.y), "f"(v.x));
    asm("cvt.rn.bf16x2.f32 %0, %1, %2;" : "=r"(u1) : "f"(v.w), "f"(v.z));
    asm volatile("st.shared.v2.b32 [%0], {%1, %2};" :: "r"(addr), "r"(u0), "r"(u1));
}
__device__ __forceinline__ uint32_t smem_u32(const void* p){
    uint32_t a; asm("{ .reg .u64 t; cvta.to.shared.u64 t, %1; cvt.u32.u64 %0, t; }" : "=r"(a) : "l"(p));
    return a;
}

// XOR swizzle inside a 64-byte bf16 row: toggle bits 3..5 by (row&7)
#define SWZ(row, kbyte) (((uint32_t)(row)) * 64u + (((uint32_t)(kbyte)) ^ ((((uint32_t)(row)) & 7u) << 3)))

// ---------------- GEMM: g_sims = features @ bank^T (bf16 tensor cores) ---------
// BM=BN=128, BK=32 (bf16). 512 threads = 16 warps (4 in M x 4 in N), warp 32x32.
constexpr int BM = 128, BN = 128, BK = 32;
constexpr int TILE_B = BM * 64;                 // 8192 bytes per operand buffer

__global__ void __launch_bounds__(512, 1)
gemm_kernel(const float* __restrict__ A, const float* __restrict__ Bk)
{
    __shared__ char smA[2 * TILE_B];
    __shared__ char smB[2 * TILE_B];
    const uint32_t abase = smem_u32(smA);
    const uint32_t bbase = smem_u32(smB);

    const int tid  = threadIdx.x;
    const int lane = tid & 31;
    const int warp = tid >> 5;
    const int grp  = lane >> 2;          // 0..7
    const int tig  = lane & 3;           // 0..3
    const int wm   = (warp & 3) * 32;
    const int wn   = (warp >> 2) * 32;
    const int m0   = blockIdx.x * BM;    // 2 m-tiles
    const int n0   = blockIdx.y * BN;    // 384 n-tiles

    float acc[2][4][4] = {};

    // global-load mapping: idx covers 128 rows x 8 float4-cols
    const int row_g = tid >> 3;                 // with it*512 offset below
    const int c4    = (tid & 7) * 4;            // float column
    const int kb_st = (tid & 7) * 8;            // smem byte column (bf16)

    const float* Ag = A  + (size_t)m0 * D_;
    const float* Bg = Bk + (size_t)n0 * D_;

    // preload slab 0
    #pragma unroll
    for (int it = 0; it < 2; ++it) {
        const int row = row_g + it * 64;
        float4 va = *(const float4*)(Ag + (size_t)row * D_ + c4);
        float4 vb = *(const float4*)(Bg + (size_t)row * D_ + c4);
        sts_bf16x4(abase + SWZ(row, kb_st), va);
        sts_bf16x4(bbase + SWZ(row, kb_st), vb);
    }
    __syncthreads();

    const int NT = D_ / BK;   // 64
    float4 ra[2], rb[2];

    for (int kt = 0; kt < NT; ++kt) {
        const int cur = kt & 1;

        if (kt + 1 < NT) {
            const int kc = (kt + 1) * BK;
            #pragma unroll
            for (int it = 0; it < 2; ++it) {
                const int row = row_g + it * 64;
                ra[it] = *(const float4*)(Ag + (size_t)row * D_ + kc + c4);
                rb[it] = *(const float4*)(Bg + (size_t)row * D_ + kc + c4);
            }
        }

        const uint32_t Ac = abase + cur * TILE_B;
        const uint32_t Bc = bbase + cur * TILE_B;

        #pragma unroll
        for (int ks = 0; ks < 2; ++ks) {
            const int kb = ks * 32 + tig * 4;    // fragment kbyte (lo half)
            uint32_t af[2][4], bf[4][2];
            #pragma unroll
            for (int mt = 0; mt < 2; ++mt) {
                const int r = wm + mt * 16 + grp;
                asm volatile("ld.shared.b32 %0, [%1];" : "=r"(af[mt][0]) : "r"(Ac + SWZ(r,     kb)));
                asm volatile("ld.shared.b32 %0, [%1];" : "=r"(af[mt][1]) : "r"(Ac + SWZ(r + 8, kb)));
                asm volatile("ld.shared.b32 %0, [%1];" : "=r"(af[mt][2]) : "r"(Ac + SWZ(r,     kb + 16)));
                asm volatile("ld.shared.b32 %0, [%1];" : "=r"(af[mt][3]) : "r"(Ac + SWZ(r + 8, kb + 16)));
            }
            #pragma unroll
            for (int nt = 0; nt < 4; ++nt) {
                const int cg = wn + nt * 8 + grp;
                asm volatile("ld.shared.b32 %0, [%1];" : "=r"(bf[nt][0]) : "r"(Bc + SWZ(cg, kb)));
                asm volatile("ld.shared.b32 %0, [%1];" : "=r"(bf[nt][1]) : "r"(Bc + SWZ(cg, kb + 16)));
            }
            #pragma unroll
            for (int mt = 0; mt < 2; ++mt)
                #pragma unroll
                for (int nt = 0; nt < 4; ++nt)
                    mma16(acc[mt][nt], af[mt], bf[nt]);
        }

        if (kt + 1 < NT) {
            const uint32_t An = abase + (cur ^ 1) * TILE_B;
            const uint32_t Bn = bbase + (cur ^ 1) * TILE_B;
            #pragma unroll
            for (int it = 0; it < 2; ++it) {
                const int row = row_g + it * 64;
                sts_bf16x4(An + SWZ(row, kb_st), ra[it]);
                sts_bf16x4(Bn + SWZ(row, kb_st), rb[it]);
            }
            __syncthreads();
        }
    }

    // epilogue (same fragment layout as m16n8k8): c0:(g,2t) c1:(g,2t+1) c2/c3: row+8
    #pragma unroll
    for (int mt = 0; mt < 2; ++mt) {
        const int r0 = m0 + wm + mt * 16 + grp;
        #pragma unroll
        for (int nt = 0; nt < 4; ++nt) {
            const int cc = n0 + wn + nt * 8 + tig * 2;
            *(float2*)(g_sims + (size_t)r0 * M_ + cc)       = make_float2(acc[mt][nt][0], acc[mt][nt][1]);
            *(float2*)(g_sims + (size_t)(r0 + 8) * M_ + cc) = make_float2(acc[mt][nt][2], acc[mt][nt][3]);
        }
    }
}

// ---------------- per-row analysis v2 -------------------------------------------
#define CAND_CAP 2048

__global__ void __launch_bounds__(256)
row_kernel(const int* __restrict__ plabel, const int* __restrict__ proxy,
           const int* __restrict__ cams,   const int* __restrict__ assoc_tab)
{
    const int i    = blockIdx.x;
    const int tid  = threadIdx.x;
    const int lane = tid & 31;
    const int wid  = tid >> 5;
    const float* rowp = g_sims + (size_t)i * M_;

    __shared__ float swv[8], swv2[8];
    __shared__ int   swi[8];
    __shared__ float cmaxv[NCAMS];
    __shared__ int   cmaxi[NCAMS];
    __shared__ float s_misc[4];      // [0] own sumexp  [2] sigma  [3] threshold
    __shared__ int   s_cnt;
    __shared__ float candv[CAND_CAP];
    __shared__ int   candi[CAND_CAP];
    __shared__ float topv[64];
    __shared__ int   topi[64];

    const int own = cams[i];

    // ---- pass A: per-cam max/argmax + global sum/sumsq --------------------------
    float lsum = 0.f, lsq = 0.f;
    for (int c = 0; c < NCAMS; ++c) {
        const float4* b4 = (const float4*)(rowp + c * P_);
        float mv = -1e30f; int mi = 0;
        #pragma unroll
        for (int it = 0; it < 8; ++it) {
            int j4 = tid + it * 256;
            float4 v = b4[j4];
            lsum += v.x + v.y + v.z + v.w;
            lsq  += v.x * v.x + v.y * v.y + v.z * v.z + v.w * v.w;
            int jb = j4 * 4;
            if (v.x > mv) { mv = v.x; mi = jb; }
            if (v.y > mv) { mv = v.y; mi = jb + 1; }
            if (v.z > mv) { mv = v.z; mi = jb + 2; }
            if (v.w > mv) { mv = v.w; mi = jb + 3; }
        }
        #pragma unroll
        for (int s = 16; s > 0; s >>= 1) {
            float ov = __shfl_down_sync(0xffffffffu, mv, s);
            int   oi = __shfl_down_sync(0xffffffffu, mi, s);
            if (ov > mv || (ov == mv && oi < mi)) { mv = ov; mi = oi; }
        }
        if (lane == 0) { swv[wid] = mv; swi[wid] = mi; }
        __syncthreads();
        if (tid == 0) {
            float bv = swv[0]; int bi = swi[0];
            for (int w = 1; w < 8; ++w)
                if (swv[w] > bv || (swv[w] == bv && swi[w] < bi)) { bv = swv[w]; bi = swi[w]; }
            cmaxv[c] = bv; cmaxi[c] = c * P_ + bi;
        }
        __syncthreads();
    }

    // ---- own-cam sumexp ----------------------------------------------------------
    {
        const float4* b4 = (const float4*)(rowp + own * P_);
        const float m = cmaxv[own];
        float le = 0.f;
        #pragma unroll
        for (int it = 0; it < 8; ++it) {
            float4 v = b4[tid + it * 256];
            le += __expf((v.x - m) * INV_BETA) + __expf((v.y - m) * INV_BETA)
                + __expf((v.z - m) * INV_BETA) + __expf((v.w - m) * INV_BETA);
        }
        #pragma unroll
        for (int s = 16; s > 0; s >>= 1) le += __shfl_down_sync(0xffffffffu, le, s);
        if (lane == 0) swv[wid] = le;
        __syncthreads();
        if (tid == 0) {
            float t = 0.f;
            for (int w = 0; w < 8; ++w) t += swv[w];
            s_misc[0] = t;
        }
        __syncthreads();
    }

    // ---- stats + threshold ---------------------------------------------------------
    #pragma unroll
    for (int s = 16; s > 0; s >>= 1) {
        lsum += __shfl_down_sync(0xffffffffu, lsum, s);
        lsq  += __shfl_down_sync(0xffffffffu, lsq,  s);
    }
    if (lane == 0) { swv[wid] = lsum; swv2[wid] = lsq; }
    __syncthreads();
    if (tid == 0) {
        float ts = 0.f, tq = 0.f;
        for (int w = 0; w < 8; ++w) { ts += swv[w]; tq += swv2[w]; }
        float mu  = ts / (float)M_;
        float var = tq / (float)M_ - mu * mu;
        float sg  = sqrtf(fmaxf(var, 1e-12f));
        s_misc[2] = sg;
        s_misc[3] = mu + 2.5f * sg;
    }
    __syncthreads();

    // ---- collect candidates (retry to land in [64, CAND_CAP]) -----------------------
    const float4* r4 = (const float4*)rowp;
    int cnt = 0;
    for (int attempt = 0; attempt < 32; ++attempt) {
        if (tid == 0) s_cnt = 0;
        __syncthreads();
        const float t = s_misc[3];
        #pragma unroll 4
        for (int it = 0; it < 48; ++it) {
            int j4 = tid + it * 256;
            float4 v = r4[j4];
            int jb = j4 * 4;
            if (v.x > t) { int p = atomicAdd(&s_cnt, 1); if (p < CAND_CAP) { candv[p] = v.x; candi[p] = jb; } }
            if (v.y > t) { int p = atomicAdd(&s_cnt, 1); if (p < CAND_CAP) { candv[p] = v.y; candi[p] = jb + 1; } }
            if (v.z > t) { int p = atomicAdd(&s_cnt, 1); if (p < CAND_CAP) { candv[p] = v.z; candi[p] = jb + 2; } }
            if (v.w > t) { int p = atomicAdd(&s_cnt, 1); if (p < CAND_CAP) { candv[p] = v.w; candi[p] = jb + 3; } }
        }
        __syncthreads();
        cnt = s_cnt;
        if (cnt >= 64 && cnt <= CAND_CAP) break;
        if (tid == 0) {
            float sg = s_misc[2]; if (sg <= 0.f) sg = 1e-6f;
            s_misc[3] = (cnt < 64) ? (s_misc[3] - 0.9f * sg) : (s_misc[3] + 0.5f * sg);
        }
        __syncthreads();
    }
    if (cnt > CAND_CAP) cnt = CAND_CAP;
    const int ntop = cnt < 64 ? cnt : 64;

    // ---- rank-sort top-64 (value desc, index asc) -------------------------------------
    for (int p = tid; p < cnt; p += 256) {
        float v = candv[p]; int id = candi[p];
        int rank = 0;
        for (int q = 0; q < cnt; ++q) {
            float w = candv[q];
            if (w > v) ++rank;
            else if (w == v && candi[q] < id) ++rank;
        }
        if (rank < 64) { topv[rank] = v; topi[rank] = id; }
    }
    __syncthreads();

    if (tid != 0) return;

    // ---- part 1: per-camera CE ----------------------------------------------------------
    const float lse1 = cmaxv[own] * INV_BETA + logf(s_misc[0]);
    g_ce[i] = lse1 - rowp[proxy[i]] * INV_BETA;

    // ---- part 2: associate loss ------------------------------------------------------------
    int aidx[A_]; float alog[A_]; float asum = 0.f;
    const int pl = plabel[i];
    #pragma unroll
    for (int j = 0; j < A_; ++j) {
        aidx[j] = assoc_tab[pl * A_ + j];
        alog[j] = rowp[aidx[j]] * INV_BETA;
        asum += alog[j];
    }
    float nl[BG_KNN]; int c2 = 0;
    for (int s = 0; s < ntop && c2 < BG_KNN; ++s) {
        const int id = topi[s];
        bool skip = false;
        #pragma unroll
        for (int j = 0; j < A_; ++j) if (aidx[j] == id) { skip = true; break; }
        if (!skip) nl[c2++] = topv[s] * INV_BETA;
    }
    float mx = -1e30f;
    for (int j = 0; j < A_; ++j) mx = fmaxf(mx, alog[j]);
    for (int j = 0; j < c2;  ++j) mx = fmaxf(mx, nl[j]);
    float se = 0.f;
    for (int j = 0; j < A_; ++j) se += expf(alog[j] - mx);
    for (int j = 0; j < c2;  ++j) se += expf(nl[j] - mx);
    g_as[i] = mx + logf(se) - asum / (float)A_;

    // ---- part 3: online loss ------------------------------------------------------------------
    bool taken[NCAMS];
    #pragma unroll
    for (int c = 0; c < NCAMS; ++c) taken[c] = false;
    int pidx[POS_K]; float plog[POS_K]; float psum = 0.f;
    #pragma unroll
    for (int s = 0; s < POS_K; ++s) {
        int best = -1; float bv = -1e38f;
        for (int c = 0; c < NCAMS; ++c)
            if (!taken[c] && cmaxv[c] > bv) { bv = cmaxv[c]; best = c; }
        taken[best] = true;
        pidx[s] = cmaxi[best];
        plog[s] = cmaxv[best] * INV_BETA;
        psum += plog[s];
    }
    float nl3[TOP_EXTRA]; int c3 = 0;
    for (int s = 0; s < ntop && c3 < TOP_EXTRA; ++s) {
        const int id = topi[s];
        if (id == pidx[0] || id == pidx[1] || id == pidx[2]) continue;
        nl3[c3++] = topv[s] * INV_BETA;
    }
    float mx3 = fmaxf(fmaxf(plog[0], plog[1]), plog[2]);
    for (int j = 0; j < c3; ++j) mx3 = fmaxf(mx3, nl3[j]);
    float se3 = 0.f;
    #pragma unroll
    for (int j = 0; j < POS_K; ++j) se3 += expf(plog[j] - mx3);
    for (int j = 0; j < c3; ++j) se3 += expf(nl3[j] - mx3);
    g_on[i] = mx3 + logf(se3) - psum / (float)POS_K;
}

// ---------------- finalize ---------------------------------------------------------
__global__ void finalize_kernel(const int* __restrict__ cams, float* __restrict__ out)
{
    const int c = threadIdx.x;
    __shared__ float parts[NCAMS];
    if (c < NCAMS) {
        float s0 = 0.f, s1 = 0.f, s2 = 0.f, n = 0.f;
        for (int r = 0; r < B_; ++r) {
            if (cams[r] == c) { s0 += g_ce[r]; s1 += g_as[r]; s2 += g_on[r]; n += 1.f; }
        }
        parts[c] = (n > 0.f) ? (0.6f * s0 + 0.7f * s1 + 0.7f * s2) / n : 0.f;
    }
    __syncthreads();
    if (c == 0) {
        float L = 0.f;
        for (int k = 0; k < NCAMS; ++k) L += parts[k];
        out[0] = L;
    }
}

// ---------------- launch --------------------------------------------------------------
extern "C" void kernel_launch(void* const* d_in, const int* in_sizes, int n_in,
                              void* d_out, int out_size)
{
    const float* features = (const float*)d_in[0];
    const float* bank     = (const float*)d_in[1];
    const int*   plabel   = (const int*)d_in[2];
    const int*   proxy    = (const int*)d_in[3];
    const int*   cams     = (const int*)d_in[4];
    const int*   assoc    = (const int*)d_in[5];
    float*       out      = (float*)d_out;

    dim3 grid(2, M_ / BN);   // m-pairs adjacent -> B-slab reuse in L2
    gemm_kernel<<<grid, 512>>>(features, bank);
    row_kernel<<<B_, 256>>>(plabel, proxy, cams, assoc);
    finalize_kernel<<<1, 32>>>(cams, out);
}

// round 16
// speedup vs baseline: 1.4546x; 1.4546x over previous
#include <cuda_runtime.h>
#include <cuda_bf16.h>
#include <stdint.h>
#include <math.h>

#define B_    256
#define D_    2048
#define NCAMS 6
#define P_    8192
#define A_    6
#define M_    49152
#define BG_KNN 50
#define POS_K  3
#define TOP_EXTRA 30
#define INV_BETA 20.0f

// ---------------- scratch -----------------------------------------------------
__device__ float g_sims[(size_t)B_ * M_];   // 50.3 MB
__device__ float g_ce[B_];
__device__ float g_as[B_];
__device__ float g_on[B_];

// ---------------- helpers -------------------------------------------------------
__device__ __forceinline__ void mma16(float d[4], const uint32_t a[4], const uint32_t b[2]){
    asm volatile(
        "mma.sync.aligned.m16n8k16.row.col.f32.bf16.bf16.f32 "
        "{%0,%1,%2,%3}, {%4,%5,%6,%7}, {%8,%9}, {%0,%1,%2,%3};"
        : "+f"(d[0]), "+f"(d[1]), "+f"(d[2]), "+f"(d[3])
        : "r"(a[0]), "r"(a[1]), "r"(a[2]), "r"(a[3]), "r"(b[0]), "r"(b[1]));
}
#define LDSM4(r0, r1, r2, r3, addr) \
    asm volatile("ldmatrix.sync.aligned.m8n8.x4.shared.b16 {%0,%1,%2,%3}, [%4];" \
        : "=r"(r0), "=r"(r1), "=r"(r2), "=r"(r3) : "r"(addr))

__device__ __forceinline__ void sts_bf16x4(uint32_t addr, float4 v){
    uint32_t u0, u1;
    asm("cvt.rn.bf16x2.f32 %0, %1, %2;" : "=r"(u0) : "f"(v.y), "f"(v.x));
    asm("cvt.rn.bf16x2.f32 %0, %1, %2;" : "=r"(u1) : "f"(v.w), "f"(v.z));
    asm volatile("st.shared.v2.b32 [%0], {%1, %2};" :: "r"(addr), "r"(u0), "r"(u1));
}
__device__ __forceinline__ uint32_t smem_u32(const void* p){
    uint32_t a; asm("{ .reg .u64 t; cvta.to.shared.u64 t, %1; cvt.u32.u64 %0, t; }" : "=r"(a) : "l"(p));
    return a;
}

// SW128 swizzle: 128B rows, 16B-granular XOR -> safe for 8B STS and 16B ldmatrix
#define SWZ128(r, kb) (((uint32_t)(r)) * 128u + (((uint32_t)(kb)) ^ ((((uint32_t)(r)) & 7u) << 4)))

// ---------------- GEMM: g_sims = features @ bank^T (bf16, ldmatrix-fed) ---------
// BM=BN=128, BK=64 bf16 (128B rows). 512 thr = 16 warps (4x4), warp tile 32x32.
constexpr int BM = 128, BN = 128, BK = 64;
constexpr int BUF = BM * 128;                   // 16 KB per operand buffer
constexpr int GEMM_SMEM = 4 * BUF;              // 64 KB (A,B double buffered)

__global__ void __launch_bounds__(512, 1)
gemm_kernel(const float* __restrict__ A, const float* __restrict__ Bk)
{
    extern __shared__ char sm[];
    const uint32_t abase = smem_u32(sm);
    const uint32_t bbase = abase + 2 * BUF;

    const int tid  = threadIdx.x;
    const int lane = tid & 31;
    const int warp = tid >> 5;
    const int wm   = (warp & 3) * 32;
    const int wn   = (warp >> 2) * 32;
    const int m0   = blockIdx.x * BM;
    const int n0   = blockIdx.y * BN;

    float acc[2][4][4] = {};

    // global-load mapping: 128 rows x 16 float4, 512 threads -> 4 iters/operand
    const int row_g = tid >> 4;                 // + it*32
    const int c4    = (tid & 15) * 4;           // float column
    const int kb_st = (tid & 15) * 8;           // smem byte column

    // ldmatrix fragment base offsets (per mt / n-pair), ks handled by XOR (ks<<5)
    uint32_t aoffs[2], boffs[2];
    #pragma unroll
    for (int mt = 0; mt < 2; ++mt) {
        const int r = wm + mt * 16 + (lane & 15);
        aoffs[mt] = SWZ128(r, (lane & 16));
    }
    #pragma unroll
    for (int np = 0; np < 2; ++np) {
        const int r = wn + np * 16 + ((lane & 16) >> 1) + (lane & 7);
        boffs[np] = SWZ128(r, ((lane & 8) << 1));
    }

    const float* Ag = A  + (size_t)m0 * D_;
    const float* Bg = Bk + (size_t)n0 * D_;

    // preload slab 0
    #pragma unroll
    for (int it = 0; it < 4; ++it) {
        const int row = row_g + it * 32;
        float4 va = *(const float4*)(Ag + (size_t)row * D_ + c4);
        float4 vb = *(const float4*)(Bg + (size_t)row * D_ + c4);
        sts_bf16x4(abase + SWZ128(row, kb_st), va);
        sts_bf16x4(bbase + SWZ128(row, kb_st), vb);
    }
    __syncthreads();

    const int NT = D_ / BK;   // 32
    float4 ra[4], rb[4];

    for (int kt = 0; kt < NT; ++kt) {
        const int cur = kt & 1;

        if (kt + 1 < NT) {
            const int kc = (kt + 1) * BK;
            #pragma unroll
            for (int it = 0; it < 4; ++it) {
                const int row = row_g + it * 32;
                ra[it] = *(const float4*)(Ag + (size_t)row * D_ + kc + c4);
                rb[it] = *(const float4*)(Bg + (size_t)row * D_ + kc + c4);
            }
        }

        const uint32_t Ac = abase + cur * BUF;
        const uint32_t Bc = bbase + cur * BUF;

        #pragma unroll
        for (int ks = 0; ks < 4; ++ks) {
            const uint32_t kx = (uint32_t)(ks << 5);
            uint32_t af[2][4], bf[4][2];
            LDSM4(af[0][0], af[0][1], af[0][2], af[0][3], Ac + (aoffs[0] ^ kx));
            LDSM4(af[1][0], af[1][1], af[1][2], af[1][3], Ac + (aoffs[1] ^ kx));
            LDSM4(bf[0][0], bf[0][1], bf[1][0], bf[1][1], Bc + (boffs[0] ^ kx));
            LDSM4(bf[2][0], bf[2][1], bf[3][0], bf[3][1], Bc + (boffs[1] ^ kx));
            #pragma unroll
            for (int mt = 0; mt < 2; ++mt)
                #pragma unroll
                for (int nt = 0; nt < 4; ++nt)
                    mma16(acc[mt][nt], af[mt], bf[nt]);
        }

        if (kt + 1 < NT) {
            const uint32_t An = abase + (cur ^ 1) * BUF;
            const uint32_t Bn = bbase + (cur ^ 1) * BUF;
            #pragma unroll
            for (int it = 0; it < 4; ++it) {
                const int row = row_g + it * 32;
                sts_bf16x4(An + SWZ128(row, kb_st), ra[it]);
                sts_bf16x4(Bn + SWZ128(row, kb_st), rb[it]);
            }
            __syncthreads();
        }
    }

    // epilogue: c0:(grp, 2tig) c1:(grp, 2tig+1) c2/c3: row+8
    const int grp = lane >> 2, tig = lane & 3;
    #pragma unroll
    for (int mt = 0; mt < 2; ++mt) {
        const int r0 = m0 + wm + mt * 16 + grp;
        #pragma unroll
        for (int nt = 0; nt < 4; ++nt) {
            const int cc = n0 + wn + nt * 8 + tig * 2;
            *(float2*)(g_sims + (size_t)r0 * M_ + cc)       = make_float2(acc[mt][nt][0], acc[mt][nt][1]);
            *(float2*)(g_sims + (size_t)(r0 + 8) * M_ + cc) = make_float2(acc[mt][nt][2], acc[mt][nt][3]);
        }
    }
}

// ---------------- per-row analysis (512 threads) ---------------------------------
#define CAND_CAP 2048
#define RT_ 512
#define NW_ 16

__global__ void __launch_bounds__(RT_)
row_kernel(const int* __restrict__ plabel, const int* __restrict__ proxy,
           const int* __restrict__ cams,   const int* __restrict__ assoc_tab)
{
    const int i    = blockIdx.x;
    const int tid  = threadIdx.x;
    const int lane = tid & 31;
    const int wid  = tid >> 5;
    const float* rowp = g_sims + (size_t)i * M_;

    __shared__ float swv[NW_], swv2[NW_];
    __shared__ int   swi[NW_];
    __shared__ float cmaxv[NCAMS];
    __shared__ int   cmaxi[NCAMS];
    __shared__ float s_misc[4];      // [0] own sumexp  [2] sigma  [3] threshold
    __shared__ int   s_cnt;
    __shared__ float candv[CAND_CAP];
    __shared__ int   candi[CAND_CAP];
    __shared__ float topv[64];
    __shared__ int   topi[64];

    const int own = cams[i];

    // ---- pass A: per-cam max/argmax + global sum/sumsq ---------------------------
    float lsum = 0.f, lsq = 0.f;
    for (int c = 0; c < NCAMS; ++c) {
        const float4* b4 = (const float4*)(rowp + c * P_);
        float mv = -1e30f; int mi = 0;
        #pragma unroll
        for (int it = 0; it < 4; ++it) {
            int j4 = tid + it * RT_;
            float4 v = b4[j4];
            lsum += v.x + v.y + v.z + v.w;
            lsq  += v.x * v.x + v.y * v.y + v.z * v.z + v.w * v.w;
            int jb = j4 * 4;
            if (v.x > mv) { mv = v.x; mi = jb; }
            if (v.y > mv) { mv = v.y; mi = jb + 1; }
            if (v.z > mv) { mv = v.z; mi = jb + 2; }
            if (v.w > mv) { mv = v.w; mi = jb + 3; }
        }
        #pragma unroll
        for (int s = 16; s > 0; s >>= 1) {
            float ov = __shfl_down_sync(0xffffffffu, mv, s);
            int   oi = __shfl_down_sync(0xffffffffu, mi, s);
            if (ov > mv || (ov == mv && oi < mi)) { mv = ov; mi = oi; }
        }
        if (lane == 0) { swv[wid] = mv; swi[wid] = mi; }
        __syncthreads();
        if (tid == 0) {
            float bv = swv[0]; int bi = swi[0];
            for (int w = 1; w < NW_; ++w)
                if (swv[w] > bv || (swv[w] == bv && swi[w] < bi)) { bv = swv[w]; bi = swi[w]; }
            cmaxv[c] = bv; cmaxi[c] = c * P_ + bi;
        }
        __syncthreads();
    }

    // ---- own-cam sumexp -------------------------------------------------------------
    {
        const float4* b4 = (const float4*)(rowp + own * P_);
        const float m = cmaxv[own];
        float le = 0.f;
        #pragma unroll
        for (int it = 0; it < 4; ++it) {
            float4 v = b4[tid + it * RT_];
            le += __expf((v.x - m) * INV_BETA) + __expf((v.y - m) * INV_BETA)
                + __expf((v.z - m) * INV_BETA) + __expf((v.w - m) * INV_BETA);
        }
        #pragma unroll
        for (int s = 16; s > 0; s >>= 1) le += __shfl_down_sync(0xffffffffu, le, s);
        if (lane == 0) swv[wid] = le;
        __syncthreads();
        if (tid == 0) {
            float t = 0.f;
            for (int w = 0; w < NW_; ++w) t += swv[w];
            s_misc[0] = t;
        }
        __syncthreads();
    }

    // ---- stats + threshold --------------------------------------------------------------
    #pragma unroll
    for (int s = 16; s > 0; s >>= 1) {
        lsum += __shfl_down_sync(0xffffffffu, lsum, s);
        lsq  += __shfl_down_sync(0xffffffffu, lsq,  s);
    }
    if (lane == 0) { swv[wid] = lsum; swv2[wid] = lsq; }
    __syncthreads();
    if (tid == 0) {
        float ts = 0.f, tq = 0.f;
        for (int w = 0; w < NW_; ++w) { ts += swv[w]; tq += swv2[w]; }
        float mu  = ts / (float)M_;
        float var = tq / (float)M_ - mu * mu;
        float sg  = sqrtf(fmaxf(var, 1e-12f));
        s_misc[2] = sg;
        s_misc[3] = mu + 2.5f * sg;
    }
    __syncthreads();

    // ---- collect candidates (retry to land in [64, CAND_CAP]) ------------------------------
    const float4* r4 = (const float4*)rowp;
    int cnt = 0;
    for (int attempt = 0; attempt < 32; ++attempt) {
        if (tid == 0) s_cnt = 0;
        __syncthreads();
        const float t = s_misc[3];
        #pragma unroll 4
        for (int it = 0; it < 24; ++it) {
            int j4 = tid + it * RT_;
            float4 v = r4[j4];
            int jb = j4 * 4;
            if (v.x > t) { int p = atomicAdd(&s_cnt, 1); if (p < CAND_CAP) { candv[p] = v.x; candi[p] = jb; } }
            if (v.y > t) { int p = atomicAdd(&s_cnt, 1); if (p < CAND_CAP) { candv[p] = v.y; candi[p] = jb + 1; } }
            if (v.z > t) { int p = atomicAdd(&s_cnt, 1); if (p < CAND_CAP) { candv[p] = v.z; candi[p] = jb + 2; } }
            if (v.w > t) { int p = atomicAdd(&s_cnt, 1); if (p < CAND_CAP) { candv[p] = v.w; candi[p] = jb + 3; } }
        }
        __syncthreads();
        cnt = s_cnt;
        if (cnt >= 64 && cnt <= CAND_CAP) break;
        if (tid == 0) {
            float sg = s_misc[2]; if (sg <= 0.f) sg = 1e-6f;
            s_misc[3] = (cnt < 64) ? (s_misc[3] - 0.9f * sg) : (s_misc[3] + 0.5f * sg);
        }
        __syncthreads();
    }
    if (cnt > CAND_CAP) cnt = CAND_CAP;
    const int ntop = cnt < 64 ? cnt : 64;

    // ---- rank-sort top-64 (value desc, index asc) ---------------------------------------------
    for (int p = tid; p < cnt; p += RT_) {
        float v = candv[p]; int id = candi[p];
        int rank = 0;
        for (int q = 0; q < cnt; ++q) {
            float w = candv[q];
            if (w > v) ++rank;
            else if (w == v && candi[q] < id) ++rank;
        }
        if (rank < 64) { topv[rank] = v; topi[rank] = id; }
    }
    __syncthreads();

    if (tid != 0) return;

    // ---- part 1: per-camera CE -------------------------------------------------------------------
    const float lse1 = cmaxv[own] * INV_BETA + logf(s_misc[0]);
    g_ce[i] = lse1 - rowp[proxy[i]] * INV_BETA;

    // ---- part 2: associate loss --------------------------------------------------------------------
    int aidx[A_]; float alog[A_]; float asum = 0.f;
    const int pl = plabel[i];
    #pragma unroll
    for (int j = 0; j < A_; ++j) {
        aidx[j] = assoc_tab[pl * A_ + j];
        alog[j] = rowp[aidx[j]] * INV_BETA;
        asum += alog[j];
    }
    float nl[BG_KNN]; int c2 = 0;
    for (int s = 0; s < ntop && c2 < BG_KNN; ++s) {
        const int id = topi[s];
        bool skip = false;
        #pragma unroll
        for (int j = 0; j < A_; ++j) if (aidx[j] == id) { skip = true; break; }
        if (!skip) nl[c2++] = topv[s] * INV_BETA;
    }
    float mx = -1e30f;
    for (int j = 0; j < A_; ++j) mx = fmaxf(mx, alog[j]);
    for (int j = 0; j < c2;  ++j) mx = fmaxf(mx, nl[j]);
    float se = 0.f;
    for (int j = 0; j < A_; ++j) se += expf(alog[j] - mx);
    for (int j = 0; j < c2;  ++j) se += expf(nl[j] - mx);
    g_as[i] = mx + logf(se) - asum / (float)A_;

    // ---- part 3: online loss -------------------------------------------------------------------------
    bool taken[NCAMS];
    #pragma unroll
    for (int c = 0; c < NCAMS; ++c) taken[c] = false;
    int pidx[POS_K]; float plog[POS_K]; float psum = 0.f;
    #pragma unroll
    for (int s = 0; s < POS_K; ++s) {
        int best = -1; float bv = -1e38f;
        for (int c = 0; c < NCAMS; ++c)
            if (!taken[c] && cmaxv[c] > bv) { bv = cmaxv[c]; best = c; }
        taken[best] = true;
        pidx[s] = cmaxi[best];
        plog[s] = cmaxv[best] * INV_BETA;
        psum += plog[s];
    }
    float nl3[TOP_EXTRA]; int c3 = 0;
    for (int s = 0; s < ntop && c3 < TOP_EXTRA; ++s) {
        const int id = topi[s];
        if (id == pidx[0] || id == pidx[1] || id == pidx[2]) continue;
        nl3[c3++] = topv[s] * INV_BETA;
    }
    float mx3 = fmaxf(fmaxf(plog[0], plog[1]), plog[2]);
    for (int j = 0; j < c3; ++j) mx3 = fmaxf(mx3, nl3[j]);
    float se3 = 0.f;
    #pragma unroll
    for (int j = 0; j < POS_K; ++j) se3 += expf(plog[j] - mx3);
    for (int j = 0; j < c3; ++j) se3 += expf(nl3[j] - mx3);
    g_on[i] = mx3 + logf(se3) - psum / (float)POS_K;
}

// ---------------- finalize ------------------------------------------------------------
__global__ void finalize_kernel(const int* __restrict__ cams, float* __restrict__ out)
{
    const int c = threadIdx.x;
    __shared__ float parts[NCAMS];
    if (c < NCAMS) {
        float s0 = 0.f, s1 = 0.f, s2 = 0.f, n = 0.f;
        for (int r = 0; r < B_; ++r) {
            if (cams[r] == c) { s0 += g_ce[r]; s1 += g_as[r]; s2 += g_on[r]; n += 1.f; }
        }
        parts[c] = (n > 0.f) ? (0.6f * s0 + 0.7f * s1 + 0.7f * s2) / n : 0.f;
    }
    __syncthreads();
    if (c == 0) {
        float L = 0.f;
        for (int k = 0; k < NCAMS; ++k) L += parts[k];
        out[0] = L;
    }
}

// ---------------- launch ----------------------------------------------------------------
extern "C" void kernel_launch(void* const* d_in, const int* in_sizes, int n_in,
                              void* d_out, int out_size)
{
    const float* features = (const float*)d_in[0];
    const float* bank     = (const float*)d_in[1];
    const int*   plabel   = (const int*)d_in[2];
    const int*   proxy    = (const int*)d_in[3];
    const int*   cams     = (const int*)d_in[4];
    const int*   assoc    = (const int*)d_in[5];
    float*       out      = (float*)d_out;

    cudaFuncSetAttribute(gemm_kernel, cudaFuncAttributeMaxDynamicSharedMemorySize, GEMM_SMEM);

    dim3 grid(2, M_ / BN);   // m-pairs adjacent -> B-slab reuse in L2
    gemm_kernel<<<grid, 512, GEMM_SMEM>>>(features, bank);
    row_kernel<<<B_, RT_>>>(plabel, proxy, cams, assoc);
    finalize_kernel<<<1, 32>>>(cams, out);
}